// round 15
// baseline (speedup 1.0000x reference)
#include <cuda_runtime.h>
#include <cuda_bf16.h>
#include <math.h>
#include <stdint.h>

#define BATCHN 4
#define SEQL   2048
#define DM     1024
#define DI     2048
#define DS     16
#define RK     64
#define XDC    128             // padded x_dbl column count (96 -> 128)
#define NTOK   (BATCHN*SEQL)   // 8192
#define NC     32              // scan chunks
#define CH     64              // chunk length

// ---------------- scratch (static device allocation; no cudaMalloc) ----------
__device__ __align__(16) __nv_bfloat16 g_xzb [(size_t)NTOK*2*DI];   // 64 MB
__device__ __align__(16) __nv_bfloat16 g_ub  [(size_t)NTOK*DI];     // 32 MB
__device__ __align__(16) __nv_bfloat16 g_dtb [(size_t)NTOK*DI];     // 32 MB
__device__ __align__(16) float         g_xdbl[(size_t)NTOK*XDC];    // 4 MB (fp32 B,C)
__device__ __align__(16) __nv_bfloat16 g_xdblb[(size_t)NTOK*XDC];   // 2 MB (bf16 dt in)
__device__ __align__(16) __nv_bfloat16 g_yb  [(size_t)NTOK*DI];     // 32 MB
__device__ __align__(16) __nv_bfloat16 g_xnb [(size_t)NTOK*DM];     // 16 MB
__device__ __align__(16) __nv_bfloat16 g_winb[(size_t)2*DI*DM];     // 8 MB
__device__ __align__(16) __nv_bfloat16 g_woutb[(size_t)DM*DI];      // 4 MB
__device__ __align__(16) __nv_bfloat16 g_xpwb[(size_t)XDC*DI];      // padded x_proj_w
__device__ __align__(16) __nv_bfloat16 g_dtwb[(size_t)DI*RK];
__device__ float g_A    [DI*DS];
__device__ float g_hend  [(size_t)BATCHN*NC*DS*DI];
__device__ float g_P     [(size_t)BATCHN*NC*DS*DI];
__device__ float g_hstart[(size_t)BATCHN*NC*DS*DI];
__device__ int   g_fast = 1;

// ---------------- helpers ----------------
__device__ __forceinline__ float softplusf(float v) {
    return v > 20.0f ? v : log1pf(__expf(v));
}
__device__ __forceinline__ float siluf(float v) {
    return v / (1.0f + __expf(-v));
}
__device__ __forceinline__ uint32_t smem_u32(const void* p) {
    uint32_t a;
    asm("{ .reg .u64 t; cvta.to.shared.u64 t, %1; cvt.u32.u64 %0, t; }" : "=r"(a) : "l"(p));
    return a;
}
__device__ __forceinline__ void cp16(uint32_t sm, const void* g) {
    asm volatile("cp.async.cg.shared.global [%0], [%1], 16;" :: "r"(sm), "l"(g));
}
__device__ __forceinline__ void ldsm4(uint32_t* r, uint32_t addr) {
    asm volatile("ldmatrix.sync.aligned.m8n8.x4.shared.b16 {%0,%1,%2,%3}, [%4];"
        : "=r"(r[0]), "=r"(r[1]), "=r"(r[2]), "=r"(r[3]) : "r"(addr));
}
__device__ __forceinline__ void mma16816(float* c, const uint32_t* a, uint32_t b0, uint32_t b1) {
    asm volatile("mma.sync.aligned.m16n8k16.row.col.f32.bf16.bf16.f32 "
        "{%0,%1,%2,%3}, {%4,%5,%6,%7}, {%8,%9}, {%0,%1,%2,%3};"
        : "+f"(c[0]), "+f"(c[1]), "+f"(c[2]), "+f"(c[3])
        : "r"(a[0]), "r"(a[1]), "r"(a[2]), "r"(a[3]), "r"(b0), "r"(b1));
}
__device__ __forceinline__ uint32_t packbf2(float a, float b) {
    __nv_bfloat162 h = __floats2bfloat162_rn(a, b);
    return *(uint32_t*)&h;
}

// =====================================================================
// hgemm256: 128x256 CTA tile, BK=64, 4-stage cp.async pipeline,
// 8 warps (2M x 4N), warp tile 64x64. One __syncthreads per K-chunk.
// EPI 2: fp32 store + residual.  EPI 3: bf16 store.
// SMEM: 4 stages x (A 16KB + B 32KB) = 192KB.
// =====================================================================
#define HG2_SMEM 196608
template<int EPI>
__global__ __launch_bounds__(256, 1)
void hgemm256(const __nv_bfloat16* __restrict__ A, int lda,
              const __nv_bfloat16* __restrict__ W, int ldw,
              void* __restrict__ Cv, int ldc, int K,
              const float* __restrict__ EP)
{
    extern __shared__ char smem_raw[];
    const uint32_t sbase = smem_u32(smem_raw);
    const int tid = threadIdx.x, wid = tid >> 5, lane = tid & 31;
    const int mBase = blockIdx.y * 128, nBase = blockIdx.x * 256;
    const int warpM = (wid >> 2) * 64;   // 0 or 64
    const int warpN = (wid & 3) * 64;    // 0,64,128,192

    float acc[4][8][4];
#pragma unroll
    for (int i = 0; i < 4; i++)
#pragma unroll
        for (int j = 0; j < 8; j++)
#pragma unroll
            for (int q = 0; q < 4; q++) acc[i][j][q] = 0.f;

    const int nk = K / 64;

    auto load_stage = [&](int kt) {
        const int st = kt & 3;
        const uint32_t aB = sbase + st * 49152;
        const uint32_t bB = aB + 16384;
        const __nv_bfloat16* Ag = A + (size_t)mBase * lda + kt * 64;
        const __nv_bfloat16* Wg = W + (size_t)nBase * ldw + kt * 64;
#pragma unroll
        for (int p = 0; p < 4; p++) {
            int idx = p * 256 + tid;           // 0..1023: 128 rows x 8 chunks
            int row = idx >> 3, u = idx & 7;
            int su = row * 8 + (u ^ (row & 7));
            cp16(aB + su * 16, Ag + (size_t)row * lda + u * 8);
        }
#pragma unroll
        for (int p = 0; p < 8; p++) {
            int idx = p * 256 + tid;           // 0..2047: 256 rows x 8 chunks
            int row = idx >> 3, u = idx & 7;
            int su = row * 8 + (u ^ (row & 7));
            cp16(bB + su * 16, Wg + (size_t)row * ldw + u * 8);
        }
        asm volatile("cp.async.commit_group;" ::: "memory");
    };

#pragma unroll
    for (int s = 0; s < 3; s++)
        if (s < nk) load_stage(s);

    for (int kt = 0; kt < nk; kt++) {
        const int rem = nk - 1 - kt;
        if (rem >= 2)      asm volatile("cp.async.wait_group 2;" ::: "memory");
        else if (rem == 1) asm volatile("cp.async.wait_group 1;" ::: "memory");
        else               asm volatile("cp.async.wait_group 0;" ::: "memory");
        __syncthreads();                     // publish stage kt; protect buf (kt+3)&3
        if (kt + 3 < nk) load_stage(kt + 3); // overlaps with compute below
        const int st = kt & 3;
        const uint32_t aB = sbase + st * 49152;
        const uint32_t bB = aB + 16384;
#pragma unroll
        for (int ks = 0; ks < 4; ks++) {
            uint32_t afr[4][4];
#pragma unroll
            for (int mt = 0; mt < 4; mt++) {
                int r = warpM + mt * 16 + (lane & 15);
                int u = ks * 2 + (lane >> 4);
                ldsm4(afr[mt], aB + (r * 8 + (u ^ (r & 7))) * 16);
            }
            uint32_t bfr[4][4];
#pragma unroll
            for (int nt = 0; nt < 4; nt++) {
                int r = warpN + nt * 16 + (lane & 15);
                int u = ks * 2 + (lane >> 4);
                ldsm4(bfr[nt], bB + (r * 8 + (u ^ (r & 7))) * 16);
            }
#pragma unroll
            for (int mt = 0; mt < 4; mt++)
#pragma unroll
                for (int j = 0; j < 8; j++)
                    mma16816(acc[mt][j], afr[mt], bfr[j >> 1][j & 1], bfr[j >> 1][(j & 1) + 2]);
        }
    }

    // epilogue
#pragma unroll
    for (int mt = 0; mt < 4; mt++) {
        const int row0 = mBase + warpM + mt * 16 + (lane >> 2);
        const int row1 = row0 + 8;
#pragma unroll
        for (int j = 0; j < 8; j++) {
            const int col = nBase + warpN + j * 8 + (lane & 3) * 2;
            float v00 = acc[mt][j][0], v01 = acc[mt][j][1];
            float v10 = acc[mt][j][2], v11 = acc[mt][j][3];
            if (EPI == 2) {
                float* C = (float*)Cv;
                float2 r0 = *(const float2*)&EP[(size_t)row0 * ldc + col];
                float2 r1 = *(const float2*)&EP[(size_t)row1 * ldc + col];
                *(float2*)&C[(size_t)row0 * ldc + col] = make_float2(v00 + r0.x, v01 + r0.y);
                *(float2*)&C[(size_t)row1 * ldc + col] = make_float2(v10 + r1.x, v11 + r1.y);
            } else {
                __nv_bfloat16* C = (__nv_bfloat16*)Cv;
                *(uint32_t*)&C[(size_t)row0 * ldc + col] = packbf2(v00, v01);
                *(uint32_t*)&C[(size_t)row1 * ldc + col] = packbf2(v10, v11);
            }
        }
    }
}

// =====================================================================
// hgemm128: 128x128 tile, BK=64, 2-stage (for small-K / small-grid GEMMs)
// EPI 4: softplus(acc + EP[col]) -> bf16.  EPI 5: fp32 store + bf16 copy.
// =====================================================================
#define HG_SMEM 65536
template<int EPI>
__global__ __launch_bounds__(256, 2)
void hgemm(const __nv_bfloat16* __restrict__ A, int lda,
           const __nv_bfloat16* __restrict__ W, int ldw,
           void* __restrict__ Cv, int ldc, int K,
           const float* __restrict__ EP,
           __nv_bfloat16* __restrict__ aux)
{
    extern __shared__ char smem_raw[];
    const uint32_t abase = smem_u32(smem_raw);
    const uint32_t bbase = abase + 32768;
    const int tid = threadIdx.x, wid = tid >> 5, lane = tid & 31;
    const int mBase = blockIdx.y * 128, nBase = blockIdx.x * 128;
    const int warpM = (wid >> 2) * 64;
    const int warpN = (wid & 3) * 32;

    float acc[4][4][4];
#pragma unroll
    for (int i = 0; i < 4; i++)
#pragma unroll
        for (int j = 0; j < 4; j++)
#pragma unroll
            for (int q = 0; q < 4; q++) acc[i][j][q] = 0.f;

    const int nk = K / 64;

    auto load_stage = [&](int kt) {
        const int b = kt & 1;
        const uint32_t aB = abase + b * 16384;
        const uint32_t bB = bbase + b * 16384;
        const __nv_bfloat16* Ag = A + (size_t)mBase * lda + kt * 64;
        const __nv_bfloat16* Wg = W + (size_t)nBase * ldw + kt * 64;
#pragma unroll
        for (int p = 0; p < 4; p++) {
            int idx = p * 256 + tid;
            int row = idx >> 3, u = idx & 7;
            int su = row * 8 + (u ^ (row & 7));
            cp16(aB + su * 16, Ag + (size_t)row * lda + u * 8);
            cp16(bB + su * 16, Wg + (size_t)row * ldw + u * 8);
        }
        asm volatile("cp.async.commit_group;" ::: "memory");
    };

    load_stage(0);
    for (int kt = 0; kt < nk; kt++) {
        if (kt + 1 < nk) {
            load_stage(kt + 1);
            asm volatile("cp.async.wait_group 1;" ::: "memory");
        } else {
            asm volatile("cp.async.wait_group 0;" ::: "memory");
        }
        __syncthreads();
        const int b = kt & 1;
        const uint32_t aB = abase + b * 16384;
        const uint32_t bB = bbase + b * 16384;
#pragma unroll
        for (int ks = 0; ks < 4; ks++) {
            uint32_t afr[4][4];
#pragma unroll
            for (int mt = 0; mt < 4; mt++) {
                int r = warpM + mt * 16 + (lane & 15);
                int u = ks * 2 + (lane >> 4);
                ldsm4(afr[mt], aB + (r * 8 + (u ^ (r & 7))) * 16);
            }
            uint32_t bfr[2][4];
#pragma unroll
            for (int nt = 0; nt < 2; nt++) {
                int r = warpN + nt * 16 + (lane & 15);
                int u = ks * 2 + (lane >> 4);
                ldsm4(bfr[nt], bB + (r * 8 + (u ^ (r & 7))) * 16);
            }
#pragma unroll
            for (int mt = 0; mt < 4; mt++)
#pragma unroll
                for (int j = 0; j < 4; j++)
                    mma16816(acc[mt][j], afr[mt], bfr[j >> 1][j & 1], bfr[j >> 1][(j & 1) + 2]);
        }
        __syncthreads();
    }

#pragma unroll
    for (int mt = 0; mt < 4; mt++) {
        const int row0 = mBase + warpM + mt * 16 + (lane >> 2);
        const int row1 = row0 + 8;
#pragma unroll
        for (int j = 0; j < 4; j++) {
            const int col = nBase + warpN + j * 8 + (lane & 3) * 2;
            float v00 = acc[mt][j][0], v01 = acc[mt][j][1];
            float v10 = acc[mt][j][2], v11 = acc[mt][j][3];
            if (EPI == 4) {
                __nv_bfloat16* C = (__nv_bfloat16*)Cv;
                float b0 = EP[col], b1 = EP[col + 1];
                *(uint32_t*)&C[(size_t)row0 * ldc + col] =
                    packbf2(softplusf(v00 + b0), softplusf(v01 + b1));
                *(uint32_t*)&C[(size_t)row1 * ldc + col] =
                    packbf2(softplusf(v10 + b0), softplusf(v11 + b1));
            } else if (EPI == 5) {
                float* C = (float*)Cv;
                *(float2*)&C[(size_t)row0 * ldc + col] = make_float2(v00, v01);
                *(float2*)&C[(size_t)row1 * ldc + col] = make_float2(v10, v11);
                *(uint32_t*)&aux[(size_t)row0 * ldc + col] = packbf2(v00, v01);
                *(uint32_t*)&aux[(size_t)row1 * ldc + col] = packbf2(v10, v11);
            }
        }
    }
}

// ---------------- prep ----------------
__global__ void k_prepA(const float* __restrict__ A_log) {
    int i = blockIdx.x * blockDim.x + threadIdx.x;
    if (i < DI * DS) {
        float a = -__expf(A_log[i]);
        g_A[i] = a;
        int s = i & (DS - 1);
        float expect = -(float)(s + 1);
        if (fabsf(a - expect) > 1e-3f * (float)(s + 1))
            atomicExch(&g_fast, 0);
    }
}

__global__ void k_f2b(const float* __restrict__ src, __nv_bfloat16* __restrict__ dst, int n4) {
    int i = blockIdx.x * blockDim.x + threadIdx.x;
    if (i < n4) {
        float4 v = ((const float4*)src)[i];
        uint2 o; o.x = packbf2(v.x, v.y); o.y = packbf2(v.z, v.w);
        ((uint2*)dst)[i] = o;
    }
}

__global__ void k_padxw(const float* __restrict__ src) {
    int i = blockIdx.x * blockDim.x + threadIdx.x;
    if (i >= XDC * (DI / 4)) return;
    int row = i / (DI / 4), cq = i % (DI / 4);
    uint2 o;
    if (row < 96) {
        float4 v = *(const float4*)&src[(size_t)row * DI + cq * 4];
        o.x = packbf2(v.x, v.y); o.y = packbf2(v.z, v.w);
    } else {
        o.x = 0u; o.y = 0u;
    }
    ((uint2*)g_xpwb)[i] = o;
}

// ---------------- RMSNorm -> bf16 ----------------
__global__ __launch_bounds__(256)
void k_rmsnorm(const float* __restrict__ x, const float* __restrict__ w) {
    int row = blockIdx.x;
    const float4* xr = reinterpret_cast<const float4*>(x) + (size_t)row * (DM / 4);
    float4 v = xr[threadIdx.x];
    float ss = v.x * v.x + v.y * v.y + v.z * v.z + v.w * v.w;
#pragma unroll
    for (int o = 16; o > 0; o >>= 1) ss += __shfl_xor_sync(0xffffffffu, ss, o);
    __shared__ float red[8];
    __shared__ float scale_s;
    int wid = threadIdx.x >> 5;
    if ((threadIdx.x & 31) == 0) red[wid] = ss;
    __syncthreads();
    if (threadIdx.x == 0) {
        float t = 0.f;
#pragma unroll
        for (int i = 0; i < 8; i++) t += red[i];
        scale_s = rsqrtf(t * (1.0f / (float)DM) + 1.1920929e-7f);
    }
    __syncthreads();
    float s = scale_s;
    float4 wv = reinterpret_cast<const float4*>(w)[threadIdx.x];
    uint2 o;
    o.x = packbf2(v.x * s * wv.x, v.y * s * wv.y);
    o.y = packbf2(v.z * s * wv.z, v.w * s * wv.w);
    ((uint2*)g_xnb)[(size_t)row * (DM / 4) + threadIdx.x] = o;
}

// ---------------- causal depthwise conv1d + SiLU ----------------
__global__ void k_conv(const float* __restrict__ cw, const float* __restrict__ cb) {
    int i = blockIdx.x * blockDim.x + threadIdx.x;
    if (i >= NTOK * (DI / 4)) return;
    int dq = i % (DI / 4);
    int t  = i / (DI / 4);
    int d4 = dq * 4;
    int b = t >> 11, l = t & (SEQL - 1);
    float4 acc = *(const float4*)&cb[d4];
    float wreg[4][4];
#pragma unroll
    for (int r = 0; r < 4; r++) {
        float4 wr = *(const float4*)&cw[(d4 + r) * 4];
        wreg[r][0] = wr.x; wreg[r][1] = wr.y; wreg[r][2] = wr.z; wreg[r][3] = wr.w;
    }
#pragma unroll
    for (int j = 0; j < 4; j++) {
        int lj = l - 3 + j;
        if (lj >= 0) {
            uint2 xv = *(const uint2*)&g_xzb[(size_t)(b * SEQL + lj) * (2 * DI) + d4];
            float2 x01 = __bfloat1622float2(*(__nv_bfloat162*)&xv.x);
            float2 x23 = __bfloat1622float2(*(__nv_bfloat162*)&xv.y);
            acc.x = fmaf(x01.x, wreg[0][j], acc.x);
            acc.y = fmaf(x01.y, wreg[1][j], acc.y);
            acc.z = fmaf(x23.x, wreg[2][j], acc.z);
            acc.w = fmaf(x23.y, wreg[3][j], acc.w);
        }
    }
    uint2 o;
    o.x = packbf2(siluf(acc.x), siluf(acc.y));
    o.y = packbf2(siluf(acc.z), siluf(acc.w));
    *(uint2*)&g_ub[(size_t)t * DI + d4] = o;
}

// ---------------- scan phase 1 ----------------
__global__ __launch_bounds__(128)
void k_scan1() {
    __shared__ float sBC[CH * 32];
    const int b = blockIdx.y, c = blockIdx.z;
    const int l0 = c * CH;
    const int tid = threadIdx.x;
    for (int i = tid; i < CH * 8; i += 128) {
        int r = i >> 3, cq = i & 7;
        *(float4*)&sBC[r * 32 + cq * 4] =
            *(const float4*)&g_xdbl[(size_t)(b * SEQL + l0 + r) * XDC + 64 + cq * 4];
    }
    __syncthreads();
    const int d0 = blockIdx.x * 256 + tid * 2;
    float h0[DS], h1[DS];
#pragma unroll
    for (int s = 0; s < DS; s++) { h0[s] = 0.f; h1[s] = 0.f; }
    const __nv_bfloat162* dtp =
        (const __nv_bfloat162*)&g_dtb[(size_t)(b * SEQL + l0) * DI + d0];
    const __nv_bfloat162* up =
        (const __nv_bfloat162*)&g_ub[(size_t)(b * SEQL + l0) * DI + d0];
    const size_t sb = (size_t)(b * NC + c) * DS * DI + d0;
    const int fast = g_fast;

    if (fast) {
        float q0 = 1.f, q1 = 1.f;
        for (int t = 0; t < CH; t++) {
            float2 dt2 = __bfloat1622float2(dtp[(size_t)t * (DI / 2)]);
            float2 u2  = __bfloat1622float2(up[(size_t)t * (DI / 2)]);
            float e0 = __expf(-dt2.x), e1 = __expf(-dt2.y);
            float w0 = dt2.x * u2.x,   w1 = dt2.y * u2.y;
            q0 *= e0; q1 *= e1;
            float p0 = e0, p1 = e1;
#pragma unroll
            for (int s = 0; s < DS; s++) {
                float Bs = sBC[t * 32 + s];
                h0[s] = fmaf(p0, h0[s], w0 * Bs);
                h1[s] = fmaf(p1, h1[s], w1 * Bs);
                p0 *= e0; p1 *= e1;
            }
        }
#pragma unroll
        for (int s = 0; s < DS; s++)
            *(float2*)&g_hend[sb + (size_t)s * DI] = make_float2(h0[s], h1[s]);
        float pp0 = q0, pp1 = q1;
#pragma unroll
        for (int s = 0; s < DS; s++) {
            *(float2*)&g_P[sb + (size_t)s * DI] = make_float2(pp0, pp1);
            pp0 *= q0; pp1 *= q1;
        }
    } else {
        float a0[DS], a1[DS], P0[DS], P1[DS];
#pragma unroll
        for (int s = 0; s < DS; s++) {
            a0[s] = g_A[d0 * DS + s];
            a1[s] = g_A[(d0 + 1) * DS + s];
            P0[s] = 1.f; P1[s] = 1.f;
        }
        for (int t = 0; t < CH; t++) {
            float2 dt2 = __bfloat1622float2(dtp[(size_t)t * (DI / 2)]);
            float2 u2  = __bfloat1622float2(up[(size_t)t * (DI / 2)]);
            float w0 = dt2.x * u2.x, w1 = dt2.y * u2.y;
#pragma unroll
            for (int s = 0; s < DS; s++) {
                float Bs = sBC[t * 32 + s];
                float dA0 = __expf(dt2.x * a0[s]);
                float dA1 = __expf(dt2.y * a1[s]);
                h0[s] = fmaf(dA0, h0[s], w0 * Bs);
                h1[s] = fmaf(dA1, h1[s], w1 * Bs);
                P0[s] *= dA0; P1[s] *= dA1;
            }
        }
#pragma unroll
        for (int s = 0; s < DS; s++) {
            *(float2*)&g_hend[sb + (size_t)s * DI] = make_float2(h0[s], h1[s]);
            *(float2*)&g_P  [sb + (size_t)s * DI] = make_float2(P0[s], P1[s]);
        }
    }
}

// ---------------- scan phase 2 ----------------
__global__ void k_scan2() {
    int idx = blockIdx.x * blockDim.x + threadIdx.x;
    if (idx >= BATCHN * DS * DI) return;
    int d = idx & (DI - 1);
    int s = (idx >> 11) & (DS - 1);
    int b = idx >> 15;
    float hs = 0.f;
    size_t base = ((size_t)(b * NC) * DS + s) * DI + d;
    const size_t cstride = (size_t)DS * DI;
    for (int c = 0; c < NC; c++) {
        size_t off = base + (size_t)c * cstride;
        g_hstart[off] = hs;
        hs = g_P[off] * hs + g_hend[off];
    }
}

// ---------------- scan phase 3 ----------------
__global__ __launch_bounds__(128)
void k_scan3(const float* __restrict__ Dp_) {
    __shared__ float sBC[CH * 32];
    const int b = blockIdx.y, c = blockIdx.z;
    const int l0 = c * CH;
    const int tid = threadIdx.x;
    for (int i = tid; i < CH * 8; i += 128) {
        int r = i >> 3, cq = i & 7;
        *(float4*)&sBC[r * 32 + cq * 4] =
            *(const float4*)&g_xdbl[(size_t)(b * SEQL + l0 + r) * XDC + 64 + cq * 4];
    }
    __syncthreads();
    const int d0 = blockIdx.x * 256 + tid * 2;
    const size_t sb = (size_t)(b * NC + c) * DS * DI + d0;
    float h0[DS], h1[DS];
#pragma unroll
    for (int s = 0; s < DS; s++) {
        float2 hv = *(const float2*)&g_hstart[sb + (size_t)s * DI];
        h0[s] = hv.x; h1[s] = hv.y;
    }
    float2 Dv = *(const float2*)&Dp_[d0];
    const __nv_bfloat162* dtp =
        (const __nv_bfloat162*)&g_dtb[(size_t)(b * SEQL + l0) * DI + d0];
    const __nv_bfloat162* up =
        (const __nv_bfloat162*)&g_ub[(size_t)(b * SEQL + l0) * DI + d0];
    const __nv_bfloat162* zp =
        (const __nv_bfloat162*)&g_xzb[(size_t)(b * SEQL + l0) * (2 * DI) + DI + d0];
    __nv_bfloat162* yp = (__nv_bfloat162*)&g_yb[(size_t)(b * SEQL + l0) * DI + d0];
    const int fast = g_fast;

    if (fast) {
        for (int t = 0; t < CH; t++) {
            float2 dt2 = __bfloat1622float2(dtp[(size_t)t * (DI / 2)]);
            float2 u2  = __bfloat1622float2(up[(size_t)t * (DI / 2)]);
            float e0 = __expf(-dt2.x), e1 = __expf(-dt2.y);
            float w0 = dt2.x * u2.x,   w1 = dt2.y * u2.y;
            float p0 = e0, p1 = e1;
            float y0 = 0.f, y1 = 0.f;
#pragma unroll
            for (int s = 0; s < DS; s++) {
                float Bs = sBC[t * 32 + s];
                float Cs = sBC[t * 32 + 16 + s];
                h0[s] = fmaf(p0, h0[s], w0 * Bs);
                h1[s] = fmaf(p1, h1[s], w1 * Bs);
                y0 = fmaf(h0[s], Cs, y0);
                y1 = fmaf(h1[s], Cs, y1);
                p0 *= e0; p1 *= e1;
            }
            float2 z2 = __bfloat1622float2(zp[(size_t)t * DI]);
            float o0 = (y0 + Dv.x * u2.x) * siluf(z2.x);
            float o1 = (y1 + Dv.y * u2.y) * siluf(z2.y);
            yp[(size_t)t * (DI / 2)] = __floats2bfloat162_rn(o0, o1);
        }
    } else {
        float a0[DS], a1[DS];
#pragma unroll
        for (int s = 0; s < DS; s++) {
            a0[s] = g_A[d0 * DS + s];
            a1[s] = g_A[(d0 + 1) * DS + s];
        }
        for (int t = 0; t < CH; t++) {
            float2 dt2 = __bfloat1622float2(dtp[(size_t)t * (DI / 2)]);
            float2 u2  = __bfloat1622float2(up[(size_t)t * (DI / 2)]);
            float w0 = dt2.x * u2.x, w1 = dt2.y * u2.y;
            float y0 = 0.f, y1 = 0.f;
#pragma unroll
            for (int s = 0; s < DS; s++) {
                float Bs = sBC[t * 32 + s];
                float Cs = sBC[t * 32 + 16 + s];
                float dA0 = __expf(dt2.x * a0[s]);
                float dA1 = __expf(dt2.y * a1[s]);
                h0[s] = fmaf(dA0, h0[s], w0 * Bs);
                h1[s] = fmaf(dA1, h1[s], w1 * Bs);
                y0 = fmaf(h0[s], Cs, y0);
                y1 = fmaf(h1[s], Cs, y1);
            }
            float2 z2 = __bfloat1622float2(zp[(size_t)t * DI]);
            float o0 = (y0 + Dv.x * u2.x) * siluf(z2.x);
            float o1 = (y1 + Dv.y * u2.y) * siluf(z2.y);
            yp[(size_t)t * (DI / 2)] = __floats2bfloat162_rn(o0, o1);
        }
    }
}

// ---------------- launcher ----------------
extern "C" void kernel_launch(void* const* d_in, const int* in_sizes, int n_in,
                              void* d_out, int out_size) {
    (void)in_sizes; (void)n_in; (void)out_size;
    const float* x          = (const float*)d_in[0];
    const float* norm_w     = (const float*)d_in[1];
    const float* in_proj_w  = (const float*)d_in[2];
    const float* conv_w     = (const float*)d_in[3];
    const float* conv_b     = (const float*)d_in[4];
    const float* x_proj_w   = (const float*)d_in[5];
    const float* dt_proj_w  = (const float*)d_in[6];
    const float* dt_proj_b  = (const float*)d_in[7];
    const float* A_log      = (const float*)d_in[8];
    const float* D_param    = (const float*)d_in[9];
    const float* out_proj_w = (const float*)d_in[10];
    float* out = (float*)d_out;

    __nv_bfloat16 *p_xzb, *p_ub, *p_dtb, *p_xdblb, *p_yb, *p_xnb;
    __nv_bfloat16 *p_winb, *p_woutb, *p_xpwb, *p_dtwb;
    float *p_xdbl;
    cudaGetSymbolAddress((void**)&p_xzb,   g_xzb);
    cudaGetSymbolAddress((void**)&p_ub,    g_ub);
    cudaGetSymbolAddress((void**)&p_dtb,   g_dtb);
    cudaGetSymbolAddress((void**)&p_xdbl,  g_xdbl);
    cudaGetSymbolAddress((void**)&p_xdblb, g_xdblb);
    cudaGetSymbolAddress((void**)&p_yb,    g_yb);
    cudaGetSymbolAddress((void**)&p_xnb,   g_xnb);
    cudaGetSymbolAddress((void**)&p_winb,  g_winb);
    cudaGetSymbolAddress((void**)&p_woutb, g_woutb);
    cudaGetSymbolAddress((void**)&p_xpwb,  g_xpwb);
    cudaGetSymbolAddress((void**)&p_dtwb,  g_dtwb);

    cudaFuncSetAttribute(hgemm256<2>, cudaFuncAttributeMaxDynamicSharedMemorySize, HG2_SMEM);
    cudaFuncSetAttribute(hgemm256<3>, cudaFuncAttributeMaxDynamicSharedMemorySize, HG2_SMEM);
    cudaFuncSetAttribute(hgemm<4>, cudaFuncAttributeMaxDynamicSharedMemorySize, HG_SMEM);
    cudaFuncSetAttribute(hgemm<5>, cudaFuncAttributeMaxDynamicSharedMemorySize, HG_SMEM);

    k_prepA<<<(DI * DS + 255) / 256, 256>>>(A_log);
    k_rmsnorm<<<NTOK, 256>>>(x, norm_w);
    k_f2b<<<((2 * DI * DM / 4) + 255) / 256, 256>>>(in_proj_w, p_winb, 2 * DI * DM / 4);
    k_f2b<<<((DM * DI / 4) + 255) / 256, 256>>>(out_proj_w, p_woutb, DM * DI / 4);
    k_f2b<<<((DI * RK / 4) + 255) / 256, 256>>>(dt_proj_w, p_dtwb, DI * RK / 4);
    k_padxw<<<((XDC * DI / 4) + 255) / 256, 256>>>(x_proj_w);

    // xz = x_norm @ in_proj_w^T   [8192 x 4096] bf16 out -- 128x256 tile
    hgemm256<3><<<dim3(2 * DI / 256, NTOK / 128), 256, HG2_SMEM>>>(
        p_xnb, DM, p_winb, DM, p_xzb, 2 * DI, DM, nullptr);

    // u = silu(conv1d(x_in) + b)   bf16 out
    k_conv<<<(NTOK * (DI / 4)) / 256, 256>>>(conv_w, conv_b);

    // x_dbl = u @ x_proj_w^T   [8192 x 128(pad)]  fp32 + bf16 copy
    hgemm<5><<<dim3(1, NTOK / 128), 256, HG_SMEM>>>(
        p_ub, DI, p_xpwb, DI, p_xdbl, XDC, DI, nullptr, p_xdblb);

    // dt = softplus(x_dbl[:, :64] @ dt_proj_w^T + b)   [8192 x 2048] bf16 out
    hgemm<4><<<dim3(DI / 128, NTOK / 128), 256, HG_SMEM>>>(
        p_xdblb, XDC, p_dtwb, RK, p_dtb, DI, RK, dt_proj_b, nullptr);

    // selective scan + fused (+D*u)*silu(z)
    k_scan1<<<dim3(DI / 256, BATCHN, NC), 128>>>();
    k_scan2<<<(BATCHN * DS * DI) / 256, 256>>>();
    k_scan3<<<dim3(DI / 256, BATCHN, NC), 128>>>(D_param);

    // out = x + y @ out_proj_w^T   [8192 x 1024]  fp32 + residual -- 128x256 tile
    hgemm256<2><<<dim3(DM / 256, NTOK / 128), 256, HG2_SMEM>>>(
        p_yb, DI, p_woutb, DI, out, DM, DI, x);
}